// round 14
// baseline (speedup 1.0000x reference)
#include <cuda_runtime.h>
#include <cuda_fp16.h>
#include <cstdint>
#include <math.h>

#define BATCH 64
#define LSEQ  48
#define EDIM  300
#define F0DIM 300
#define NEGV  (-1000000000.0f)

// ---------------- helpers ----------------
__device__ __forceinline__ uint32_t smem_u32(const void* p) {
    uint32_t a;
    asm("{ .reg .u64 t; cvta.to.shared.u64 t, %1; cvt.u32.u64 %0, t; }"
        : "=r"(a) : "l"(p));
    return a;
}
#define LDSM4(r, addr) \
    asm volatile("ldmatrix.sync.aligned.m8n8.x4.shared.b16 {%0,%1,%2,%3}, [%4];" \
        : "=r"((r)[0]), "=r"((r)[1]), "=r"((r)[2]), "=r"((r)[3]) : "r"(addr))
#define LDSM2(r, addr) \
    asm volatile("ldmatrix.sync.aligned.m8n8.x2.shared.b16 {%0,%1}, [%2];" \
        : "=r"((r)[0]), "=r"((r)[1]) : "r"(addr))
#define MMA16816(c, a, bb) \
    asm volatile("mma.sync.aligned.m16n8k16.row.col.f32.f16.f16.f32 " \
        "{%0,%1,%2,%3}, {%4,%5,%6,%7}, {%8,%9}, {%0,%1,%2,%3};" \
        : "+f"((c)[0]), "+f"((c)[1]), "+f"((c)[2]), "+f"((c)[3]) \
        : "r"((a)[0]), "r"((a)[1]), "r"((a)[2]), "r"((a)[3]), \
          "r"((bb)[0]), "r"((bb)[1]))
#define CP_ASYNC16(dst, src) \
    asm volatile("cp.async.cg.shared.global [%0], [%1], 16;" :: "r"(dst), "l"(src))
#define CP_COMMIT() asm volatile("cp.async.commit_group;" ::: "memory")
#define CP_WAIT0()  asm volatile("cp.async.wait_group 0;" ::: "memory")

// order-preserving float<->uint for atomic max
__device__ __forceinline__ unsigned enc_f(float x) {
    unsigned u = __float_as_uint(x);
    return (u & 0x80000000u) ? ~u : (u | 0x80000000u);
}
__device__ __forceinline__ float dec_f(unsigned k) {
    unsigned u = (k & 0x80000000u) ? (k & 0x7fffffffu) : ~k;
    return __uint_as_float(u);
}

// split a float2 into packed fp16 hi + lo (hi = rn(v), lo = rn(v - hi))
__device__ __forceinline__ void split2(float2 v, uint32_t& hi, uint32_t& lo) {
    __half2 h2 = __float22half2_rn(v);
    float2 hf = __half22float2(h2);
    __half2 l2 = __float22half2_rn(make_float2(v.x - hf.x, v.y - hf.y));
    hi = *(uint32_t*)&h2;
    lo = *(uint32_t*)&l2;
}

// ---------------- global scratch ----------------
__device__ float g_R[128 * LSEQ * EDIM];            // r1 (0..63), r2 (64..127)
__device__ unsigned g_Su[2 * 64 * 48 * 304];        // s1 | s2 encoded max (pre-tanh)
__device__ float g_H[64 * 600];
__device__ float g_J[64 * 300];
// pre-gathered embeddings fp16 hi/lo: [s(128)][50 rows][320], pads zeroed
__device__ __half g_Xh[128 * 50 * 320];
__device__ __half g_Xl[128 * 50 * 320];
// fc0 weights, fp16 hi/lo split, layout [fc(3)][chunk(10)][n(112)][k(64)]
__device__ uint4 g_W4h[3 * 10 * 112 * 64 / 8];
__device__ uint4 g_W4l[3 * 10 * 112 * 64 / 8];
// conv weights, fp16 hi/lo, layout [t(3)][n(320)][k(320)]
__device__ __half g_CWh[3 * 320 * 320];
__device__ __half g_CWl[3 * 320 * 320];

#define S2_OFF (64 * 48 * 304)   // 933888

// ---------------------------------------------------------------------------
// prep_all: fused gather_x + init_s + prep_w + prep_cw.
// ---------------------------------------------------------------------------
#define PA_G0 128
#define PA_G1 912
#define PA_G2 210
#define PA_G3 300

__global__ __launch_bounds__(256) void prep_all(
    const int* __restrict__ q1, const int* __restrict__ q2,
    const float* __restrict__ emb, const float* __restrict__ fc0_w,
    const float* __restrict__ conv_w)
{
    int bx = blockIdx.x, tid = threadIdx.x;
    if (bx < PA_G0) {
        int s = bx;
        int b = s & 63;
        bool side = s >= 64;
        const int* q = side ? q2 : q1;
        __shared__ int toks[48];
        if (tid < 48) toks[tid] = q[b * 48 + tid];
        __syncthreads();
        size_t base = (size_t)s * 50 * 320;
        for (int idx = tid; idx < 50 * 320; idx += 256) {
            int row = idx / 320, col = idx - row * 320;
            float v = 0.f;
            if (row >= 1 && row <= 48 && col < 300)
                v = emb[(size_t)toks[row - 1] * 300 + col];
            __half h = __float2half_rn(v);
            g_Xh[base + idx] = h;
            g_Xl[base + idx] = __float2half_rn(v - __half2float(h));
        }
        return;
    }
    bx -= PA_G0;
    if (bx < PA_G1) {
        unsigned seed = ~__float_as_uint(NEGV);
        uint4 sv = make_uint4(seed, seed, seed, seed);
        unsigned base4 = (unsigned)bx * 512 + tid;
        uint4* p = (uint4*)g_Su;
        p[base4] = sv;
        p[base4 + 256] = sv;
        return;
    }
    bx -= PA_G1;
    if (bx < PA_G2) {
        for (int e = 0; e < 4; e++) {
            int idx = (bx * 1024) + tid * 4 + e;
            int fcc = idx / 7168;
            int rem = idx - fcc * 7168;
            int n = rem >> 6, k = rem & 63;
            int f = (fcc / 10) * 112 + n;
            int kg = (fcc % 10) * 64 + k;
            float v = (f < 300 && kg < 600) ? fc0_w[(size_t)f * 600 + kg] : 0.f;
            __half h = __float2half_rn(v);
            __half l = __float2half_rn(v - __half2float(h));
            size_t o = ((size_t)fcc * 112 + n) * 64 + k;
            ((__half*)g_W4h)[o] = h;
            ((__half*)g_W4l)[o] = l;
        }
        return;
    }
    bx -= PA_G2;
    {
        for (int e = 0; e < 4; e++) {
            int idx = (bx * 1024) + tid * 4 + e;
            int t = idx / 102400;
            int rem = idx - t * 102400;
            int n = rem / 320, k = rem - n * 320;
            float v = (n < 300 && k < 300) ? conv_w[(size_t)n * 900 + k * 3 + t] : 0.f;
            __half h = __float2half_rn(v);
            __half l = __float2half_rn(v - __half2float(h));
            size_t o = ((size_t)t * 320 + n) * 320 + k;
            g_CWh[o] = h;
            g_CWl[o] = l;
        }
    }
}

// ---------------------------------------------------------------------------
// encode_tc: HMMA conv1d. grid (128, 4): x = s, y = nh (eo quarter of 80).
// 192 threads (3M x 2N warps, warp N = 40 = 5 n8 tiles). ~88.7 KB smem
// -> 2 CTAs/SM. cp.async B staging.
// ---------------------------------------------------------------------------
#define XSTR 328
#define EBST 72
#define OF_XH 0
#define OF_XL 32800
#define OF_EBH 65600
#define OF_EBL 77120
#define SME_TOTAL 88640

__global__ __launch_bounds__(192) void encode_tc(const float* __restrict__ conv_b)
{
    int s = blockIdx.x, nh = blockIdx.y;
    extern __shared__ char smc[];
    int tid = threadIdx.x, warp = tid >> 5, lane = tid & 31;

    {
        const uint4* srch = (const uint4*)(g_Xh + (size_t)s * 16000);
        const uint4* srcl = (const uint4*)(g_Xl + (size_t)s * 16000);
        for (int i = tid; i < 50 * 40; i += 192) {
            int row = i / 40, c = i - row * 40;
            *(uint4*)(smc + OF_XH + row * (XSTR * 2) + c * 16) = srch[i];
            *(uint4*)(smc + OF_XL + row * (XSTR * 2) + c * 16) = srcl[i];
        }
    }

    int mw = warp >> 1, nw = warp & 1;
    float acc[5][4];
    #pragma unroll
    for (int n8 = 0; n8 < 5; n8++)
        #pragma unroll
        for (int v = 0; v < 4; v++) acc[n8][v] = 0.f;

    uint32_t sbase = smem_u32(smc);
    uint32_t aXh = sbase + OF_XH + (uint32_t)((mw * 16 + (lane & 15)) * XSTR + ((lane >> 4) << 3)) * 2;
    uint32_t aXl = aXh + (OF_XL - OF_XH);
    uint32_t aBh = sbase + OF_EBH + (uint32_t)((nw * 40 + (lane & 7)) * EBST + (lane & 8)) * 2;
    uint32_t aBl = aBh + (OF_EBL - OF_EBH);

    for (int t = 0; t < 3; t++) {
        const char* gwh = (const char*)(g_CWh + ((size_t)t * 320 + nh * 80) * 320);
        const char* gwl = (const char*)(g_CWl + ((size_t)t * 320 + nh * 80) * 320);
        for (int c = 0; c < 5; c++) {
            __syncthreads();
            // cp.async weight chunk: 80 rows x 8 uint4 (hi + lo)
            for (int i = tid; i < 80 * 8; i += 192) {
                int n = i >> 3, kk = i & 7;
                uint32_t d = sbase + OF_EBH + (uint32_t)(n * (EBST * 2) + kk * 16);
                const size_t so = (size_t)n * 640 + c * 128 + kk * 16;
                CP_ASYNC16(d, gwh + so);
                CP_ASYNC16(d + (OF_EBL - OF_EBH), gwl + so);
            }
            CP_COMMIT();
            CP_WAIT0();
            __syncthreads();
            uint32_t aoff = (uint32_t)(t * XSTR + c * 64) * 2;
            #pragma unroll
            for (int ks = 0; ks < 4; ks++) {
                uint32_t k2 = ks * 32;
                uint32_t ah[4], al[4], bhf[5][2], blf[5][2];
                LDSM4(ah, aXh + aoff + k2);
                LDSM4(al, aXl + aoff + k2);
                #pragma unroll
                for (int n8 = 0; n8 < 5; n8++) LDSM2(bhf[n8], aBh + (uint32_t)(n8 * 8 * EBST) * 2 + k2);
                #pragma unroll
                for (int n8 = 0; n8 < 5; n8++) MMA16816(acc[n8], ah, bhf[n8]);
                #pragma unroll
                for (int n8 = 0; n8 < 5; n8++) MMA16816(acc[n8], al, bhf[n8]);
                #pragma unroll
                for (int n8 = 0; n8 < 5; n8++) LDSM2(blf[n8], aBl + (uint32_t)(n8 * 8 * EBST) * 2 + k2);
                #pragma unroll
                for (int n8 = 0; n8 < 5; n8++) MMA16816(acc[n8], ah, blf[n8]);
            }
        }
    }

    int g4 = lane >> 2, t4 = lane & 3;
    int r0 = mw * 16 + g4;
    #pragma unroll
    for (int n8 = 0; n8 < 5; n8++) {
        int eo = nh * 80 + nw * 40 + n8 * 8 + t4 * 2;
        if (eo < 300) {
            float bi = conv_b[eo];
            g_R[(size_t)(s * 48 + r0) * 300 + eo]     = tanhf(acc[n8][0] + bi);
            g_R[(size_t)(s * 48 + r0 + 8) * 300 + eo] = tanhf(acc[n8][2] + bi);
        }
        if (eo + 1 < 300) {
            float bi = conv_b[eo + 1];
            g_R[(size_t)(s * 48 + r0) * 300 + eo + 1]     = tanhf(acc[n8][1] + bi);
            g_R[(size_t)(s * 48 + r0 + 8) * 300 + eo + 1] = tanhf(acc[n8][3] + bi);
        }
    }
}

// ---------------------------------------------------------------------------
// joint_tc: single launch, NI=7, K=608, cp.async B staging, vectorized
// feature build. grid (18, 3, 64). 256 threads (8 warps 4Mx2N). (unchanged)
// ---------------------------------------------------------------------------
#define NI  7
#define AST 72
#define BST 72
#define JST 116
#define OF_BH 0
#define OF_BL 16384
#define OF_AH 32768
#define OF_AL 51200
#define OF_R1 69632
#define OF_R2 79360
#define SMB_TOTAL 98816

__global__ __launch_bounds__(256) void joint_tc(
    const int* __restrict__ q1_len, const int* __restrict__ q2_len)
{
    int it = blockIdx.x / 3, fc = blockIdx.x % 3;
    int jt = blockIdx.y, b = blockIdx.z;
    int l1 = q1_len[b], l2 = q2_len[b];
    if (it * 8 >= l1 || jt * 16 >= l2) return;

    extern __shared__ char smc[];
    float* r1s = (float*)(smc + OF_R1);   // [8][304]
    float* r2s = (float*)(smc + OF_R2);   // [16][304]
    float* smJ = (float*)smc;             // epilogue reuse

    int tid = threadIdx.x;
    int warp = tid >> 5, lane = tid & 31;
    int nw = warp & 1, mw = warp >> 1;
    const int NROWS = NI * 16;

    {
        const float4* R1 = (const float4*)(g_R + (size_t)(b * 48 + it * 8) * 300);
        const float4* R2 = (const float4*)(g_R + (size_t)((64 + b) * 48 + jt * 16) * 300);
        for (int i = tid; i < 8 * 75; i += 256) {
            int r = i / 75, c = i - r * 75;
            ((float4*)(r1s + r * 304))[c] = R1[r * 75 + c];
        }
        for (int i = tid; i < 16 * 75; i += 256) {
            int r = i / 75, c = i - r * 75;
            ((float4*)(r2s + r * 304))[c] = R2[r * 75 + c];
        }
    }

    float acc[2][NI][4];
    #pragma unroll
    for (int mi = 0; mi < 2; mi++)
        #pragma unroll
        for (int ni = 0; ni < NI; ni++)
            #pragma unroll
            for (int v = 0; v < 4; v++) acc[mi][ni][v] = 0.f;

    uint32_t sbase = smem_u32(smc);
    int arow = mw * 32 + (lane & 15);
    int acol = (lane >> 4) << 3;
    uint32_t aAh0 = sbase + OF_AH + (uint32_t)(arow * AST + acol) * 2;
    uint32_t aAh1 = aAh0 + 16 * AST * 2;
    uint32_t aAl0 = sbase + OF_AL + (uint32_t)(arow * AST + acol) * 2;
    uint32_t aAl1 = aAl0 + 16 * AST * 2;
    int brow = nw * (NI * 8) + (lane & 7);
    int bcol = lane & 8;
    uint32_t aBh = sbase + OF_BH + (uint32_t)(brow * BST + bcol) * 2;
    uint32_t aBl = sbase + OF_BL + (uint32_t)(brow * BST + bcol) * 2;

    int fp_ = tid >> 1, fhalf = tid & 1;
    const float2* r1p = (const float2*)(r1s + (fp_ >> 4) * 304);
    const float2* r2p = (const float2*)(r2s + (fp_ & 15) * 304);
    uint32_t* fdh = (uint32_t*)((__half*)(smc + OF_AH) + fp_ * AST + fhalf * 32);
    uint32_t* fdl = (uint32_t*)((__half*)(smc + OF_AL) + fp_ * AST + fhalf * 32);

    const char* gwh = (const char*)(g_W4h + (size_t)(fc * 10) * 896);
    const char* gwl = (const char*)(g_W4l + (size_t)(fc * 10) * 896);

#define JOINT_KSTEP(K2) do { \
        uint32_t ah[2][4], al[2][4], bh[NI][2], bl[NI][2]; \
        LDSM4(ah[0], aAh0 + (K2)); \
        LDSM4(ah[1], aAh1 + (K2)); \
        _Pragma("unroll") \
        for (int n8 = 0; n8 < NI; n8++) LDSM2(bh[n8], aBh + (uint32_t)(n8 * 8 * BST) * 2 + (K2)); \
        _Pragma("unroll") \
        for (int mi = 0; mi < 2; mi++) \
            _Pragma("unroll") \
            for (int ni = 0; ni < NI; ni++) MMA16816(acc[mi][ni], ah[mi], bh[ni]); \
        LDSM4(al[0], aAl0 + (K2)); \
        LDSM4(al[1], aAl1 + (K2)); \
        _Pragma("unroll") \
        for (int mi = 0; mi < 2; mi++) \
            _Pragma("unroll") \
            for (int ni = 0; ni < NI; ni++) MMA16816(acc[mi][ni], al[mi], bh[ni]); \
        _Pragma("unroll") \
        for (int n8 = 0; n8 < NI; n8++) LDSM2(bl[n8], aBl + (uint32_t)(n8 * 8 * BST) * 2 + (K2)); \
        _Pragma("unroll") \
        for (int mi = 0; mi < 2; mi++) \
            _Pragma("unroll") \
            for (int ni = 0; ni < NI; ni++) MMA16816(acc[mi][ni], ah[mi], bl[ni]); \
    } while (0)

    for (int c = 0; c < 10; c++) {
        __syncthreads();
        {
            const char* sh = gwh + (size_t)c * 896 * 16;
            const char* sl = gwl + (size_t)c * 896 * 16;
            for (int i = tid; i < NROWS * 8; i += 256) {
                int n = i >> 3, kk = i & 7;
                uint32_t d = sbase + OF_BH + (uint32_t)(n * (BST * 2) + kk * 16);
                CP_ASYNC16(d, sh + i * 16);
                CP_ASYNC16(d + (OF_BL - OF_BH), sl + i * 16);
            }
            CP_COMMIT();
        }
        if (c < 9 || fhalf == 0) {
            int kb2 = (c * 64 + fhalf * 32) >> 1;
            if (c < 4 || (c == 4 && fhalf == 0)) {
                #pragma unroll
                for (int m = 0; m < 16; m++) {
                    float2 a = r1p[kb2 + m], bb = r2p[kb2 + m];
                    uint32_t hi, lo;
                    split2(make_float2(fabsf(a.x - bb.x), fabsf(a.y - bb.y)), hi, lo);
                    fdh[m] = hi; fdl[m] = lo;
                }
            } else if (c >= 5) {
                int kp2 = kb2 - 150;
                #pragma unroll
                for (int m = 0; m < 16; m++) {
                    bool valid = (kp2 + m) < 150;  // e < 600 (c==9 tail)
                    int idx = valid ? (kp2 + m) : 0;
                    float2 a = r1p[idx], bb = r2p[idx];
                    uint32_t hi, lo;
                    split2(make_float2(a.x * bb.x, a.y * bb.y), hi, lo);
                    fdh[m] = valid ? hi : 0u;
                    fdl[m] = valid ? lo : 0u;
                }
            } else {
                #pragma unroll
                for (int m = 0; m < 16; m++) {
                    int e = (kb2 + m) * 2;
                    const float* r1f = (const float*)r1p;
                    const float* r2f = (const float*)r2p;
                    float v0, v1;
                    if (e < 300)      { v0 = fabsf(r1f[e] - r2f[e]);     v1 = (e + 1 < 300) ? fabsf(r1f[e + 1] - r2f[e + 1]) : r1f[e + 1 - 300] * r2f[e + 1 - 300]; }
                    else              { v0 = r1f[e - 300] * r2f[e - 300]; v1 = r1f[e - 299] * r2f[e - 299]; }
                    uint32_t hi, lo;
                    split2(make_float2(v0, v1), hi, lo);
                    fdh[m] = hi; fdl[m] = lo;
                }
            }
        }
        CP_WAIT0();
        __syncthreads();

        if (c < 9) {
            #pragma unroll
            for (int ks = 0; ks < 4; ks++) JOINT_KSTEP((uint32_t)(ks * 16) * 2);
        } else {
            JOINT_KSTEP(0u);
            JOINT_KSTEP((uint32_t)(16 * 2));
        }
    }
#undef JOINT_KSTEP
    __syncthreads();

    {
        int r0 = mw * 32 + (lane >> 2);
        int c0 = nw * (NI * 8) + (lane & 3) * 2;
        #pragma unroll
        for (int mi = 0; mi < 2; mi++)
            #pragma unroll
            for (int ni = 0; ni < NI; ni++) {
                int r = r0 + mi * 16, cc = c0 + ni * 8;
                smJ[r * JST + cc]           = acc[mi][ni][0];
                smJ[r * JST + cc + 1]       = acc[mi][ni][1];
                smJ[(r + 8) * JST + cc]     = acc[mi][ni][2];
                smJ[(r + 8) * JST + cc + 1] = acc[mi][ni][3];
            }
    }
    __syncthreads();

    int fbase = fc * 112;
    int flim = (fc == 2) ? 76 : 112;
    int icnt = min(8, l1 - it * 8);
    int jcnt = min(16, l2 - jt * 16);

    for (int idx = tid; idx < icnt * flim; idx += 256) {
        int i = idx / flim, f = idx - i * flim;
        float v = smJ[(i * 16) * JST + f];
        for (int j = 1; j < jcnt; j++) v = fmaxf(v, smJ[(i * 16 + j) * JST + f]);
        int ig = it * 8 + i, fg = fbase + f;
        atomicMax(&g_Su[(size_t)(b * 48 + ig) * 304 + fg], enc_f(v));
    }
    for (int idx = tid; idx < jcnt * flim; idx += 256) {
        int j = idx / flim, f = idx - j * flim;
        float v = smJ[j * JST + f];
        for (int i = 1; i < icnt; i++) v = fmaxf(v, smJ[(i * 16 + j) * JST + f]);
        int jg = jt * 16 + j, fg = fbase + f;
        atomicMax(&g_Su[S2_OFF + (size_t)(b * 48 + jg) * 304 + fg], enc_f(v));
    }
}

// ---------------------------------------------------------------------------
// pool: decode s + tanh+bias ; attention softmax ; h -> g_H
// grid (2, 64), 512 threads (16 warps).
// ---------------------------------------------------------------------------
__global__ __launch_bounds__(512) void pool_kernel(
    const int* __restrict__ q1_len, const int* __restrict__ q2_len,
    const float* __restrict__ att_w, const float* __restrict__ att_b,
    const float* __restrict__ fc0_b)
{
    int side = blockIdx.x, b = blockIdx.y;
    int l1 = q1_len[b], l2 = q2_len[b];
    int len = side ? l2 : l1;
    const unsigned* Sb = g_Su + (size_t)side * S2_OFF + (size_t)b * 48 * 304;

    extern __shared__ float sm[];
    float* sv = sm;              // [48][301]
    float* lg = sv + 48 * 301;   // [48]
    int tid = threadIdx.x;

    for (int idx = tid; idx < len * 300; idx += 512) {
        int l = idx / 300, f = idx - l * 300;
        sv[l * 301 + f] = tanhf(dec_f(Sb[(size_t)l * 304 + f]) + fc0_b[f]);
    }
    __syncthreads();

    int lane = tid & 31, warp = tid >> 5;
    const float* Rbase = g_R + (size_t)(side * 64 + b) * 48 * 300;
    for (int l = warp; l < len; l += 16) {
        float a = 0.f;
        for (int e = lane; e < 300; e += 32) {
            a += att_w[e]       * Rbase[l * 300 + e];
            a += att_w[300 + e] * sv[l * 301 + e];
        }
        #pragma unroll
        for (int d = 16; d; d >>= 1) a += __shfl_xor_sync(0xffffffffu, a, d);
        if (lane == 0) lg[l] = a + att_b[0];
    }
    __syncthreads();

    if (warp == 0) {
        float v0 = (lane < len) ? lg[lane] : NEGV;
        float v1 = (lane + 32 < len) ? lg[lane + 32] : NEGV;
        float mx = fmaxf(v0, v1);
        #pragma unroll
        for (int d = 16; d; d >>= 1) mx = fmaxf(mx, __shfl_xor_sync(0xffffffffu, mx, d));
        float e0 = (lane < len) ? expf(v0 - mx) : 0.f;
        float e1 = (lane + 32 < len) ? expf(v1 - mx) : 0.f;
        float s = e0 + e1;
        #pragma unroll
        for (int d = 16; d; d >>= 1) s += __shfl_xor_sync(0xffffffffu, s, d);
        float inv = 1.f / s;
        if (lane < len) lg[lane] = e0 * inv;
        if (lane + 32 < len) lg[lane + 32] = e1 * inv;
    }
    __syncthreads();

    for (int f = tid; f < 300; f += 512) {
        float h = 0.f;
        for (int l = 0; l < len; l++) h += lg[l] * sv[l * 301 + f];
        g_H[b * 600 + side * 300 + f] = h;
    }
}

// ---------------------------------------------------------------------------
// head1: jv = tanh(H @ fc1_w^T + b). grid (64, 5), block 256.
// ---------------------------------------------------------------------------
__global__ __launch_bounds__(256) void head1_kernel(
    const float* __restrict__ fc1_w, const float* __restrict__ fc1_b)
{
    __shared__ float Hs[600];
    __shared__ float part[256];
    int b = blockIdx.x, fb = blockIdx.y;
    int tid = threadIdx.x;
    for (int i = tid; i < 600; i += 256) Hs[i] = g_H[b * 600 + i];
    __syncthreads();
    int fl = tid >> 2, seg = tid & 3;
    int f = fb * 60 + fl;
    float acc = 0.f;
    if (fl < 60) {
        const float* w = fc1_w + (size_t)f * 600 + seg * 150;
        const float* h = Hs + seg * 150;
        #pragma unroll 6
        for (int k = 0; k < 150; k++) acc += h[k] * w[k];
    }
    part[tid] = acc;
    __syncthreads();
    if (seg == 0 && fl < 60) {
        float s = part[tid] + part[tid + 1] + part[tid + 2] + part[tid + 3];
        g_J[b * 300 + f] = tanhf(s + fc1_b[f]);
    }
}

// head2: out = jv @ fc2_w^T + b. grid 64, block 64.
__global__ __launch_bounds__(64) void head2_kernel(
    const float* __restrict__ fc2_w, const float* __restrict__ fc2_b,
    float* __restrict__ out)
{
    int b = blockIdx.x, tid = threadIdx.x;
    int c = tid >> 5, lane = tid & 31;
    float acc = 0.f;
    for (int f = lane; f < 300; f += 32)
        acc += g_J[b * 300 + f] * fc2_w[c * 300 + f];
    #pragma unroll
    for (int d = 16; d; d >>= 1) acc += __shfl_xor_sync(0xffffffffu, acc, d);
    if (lane == 0) out[b * 2 + c] = acc + fc2_b[c];
}

// ---------------------------------------------------------------------------
extern "C" void kernel_launch(void* const* d_in, const int* in_sizes, int n_in,
                              void* d_out, int out_size)
{
    const int*   q1     = (const int*)d_in[0];
    const int*   q2     = (const int*)d_in[1];
    const int*   q1_len = (const int*)d_in[2];
    const int*   q2_len = (const int*)d_in[3];
    const float* emb    = (const float*)d_in[4];
    const float* conv_w = (const float*)d_in[5];
    const float* conv_b = (const float*)d_in[6];
    const float* fc0_w  = (const float*)d_in[7];
    const float* fc0_b  = (const float*)d_in[8];
    const float* fc1_w  = (const float*)d_in[9];
    const float* fc1_b  = (const float*)d_in[10];
    const float* fc2_w  = (const float*)d_in[11];
    const float* fc2_b  = (const float*)d_in[12];
    const float* att_w  = (const float*)d_in[13];
    const float* att_b  = (const float*)d_in[14];
    float* out = (float*)d_out;

    const int smC = 48 * 301 * 4 + 48 * 4;

    cudaFuncSetAttribute(encode_tc,   cudaFuncAttributeMaxDynamicSharedMemorySize, SME_TOTAL);
    cudaFuncSetAttribute(joint_tc,    cudaFuncAttributeMaxDynamicSharedMemorySize, SMB_TOTAL);
    cudaFuncSetAttribute(pool_kernel, cudaFuncAttributeMaxDynamicSharedMemorySize, smC);

    prep_all<<<PA_G0 + PA_G1 + PA_G2 + PA_G3, 256>>>(q1, q2, emb, fc0_w, conv_w);
    encode_tc<<<dim3(128, 4), 192, SME_TOTAL>>>(conv_b);
    joint_tc<<<dim3(18, 3, 64), 256, SMB_TOTAL>>>(q1_len, q2_len);
    pool_kernel<<<dim3(2, 64), 512, smC>>>(q1_len, q2_len, att_w, att_b, fc0_b);
    head1_kernel<<<dim3(64, 5), 256>>>(fc1_w, fc1_b);
    head2_kernel<<<64, 64>>>(fc2_w, fc2_b, out);
    (void)in_sizes; (void)n_in; (void)out_size;
}

// round 15
// speedup vs baseline: 1.0269x; 1.0269x over previous
#include <cuda_runtime.h>
#include <cuda_fp16.h>
#include <cstdint>
#include <math.h>

#define BATCH 64
#define LSEQ  48
#define EDIM  300
#define F0DIM 300
#define NEGV  (-1000000000.0f)

// ---------------- helpers ----------------
__device__ __forceinline__ uint32_t smem_u32(const void* p) {
    uint32_t a;
    asm("{ .reg .u64 t; cvta.to.shared.u64 t, %1; cvt.u32.u64 %0, t; }"
        : "=r"(a) : "l"(p));
    return a;
}
#define LDSM4(r, addr) \
    asm volatile("ldmatrix.sync.aligned.m8n8.x4.shared.b16 {%0,%1,%2,%3}, [%4];" \
        : "=r"((r)[0]), "=r"((r)[1]), "=r"((r)[2]), "=r"((r)[3]) : "r"(addr))
#define LDSM2(r, addr) \
    asm volatile("ldmatrix.sync.aligned.m8n8.x2.shared.b16 {%0,%1}, [%2];" \
        : "=r"((r)[0]), "=r"((r)[1]) : "r"(addr))
#define MMA16816(c, a, bb) \
    asm volatile("mma.sync.aligned.m16n8k16.row.col.f32.f16.f16.f32 " \
        "{%0,%1,%2,%3}, {%4,%5,%6,%7}, {%8,%9}, {%0,%1,%2,%3};" \
        : "+f"((c)[0]), "+f"((c)[1]), "+f"((c)[2]), "+f"((c)[3]) \
        : "r"((a)[0]), "r"((a)[1]), "r"((a)[2]), "r"((a)[3]), \
          "r"((bb)[0]), "r"((bb)[1]))
#define CP_ASYNC16(dst, src) \
    asm volatile("cp.async.cg.shared.global [%0], [%1], 16;" :: "r"(dst), "l"(src))
#define CP_COMMIT() asm volatile("cp.async.commit_group;" ::: "memory")
#define CP_WAIT0()  asm volatile("cp.async.wait_group 0;" ::: "memory")

// order-preserving float<->uint for atomic max
__device__ __forceinline__ unsigned enc_f(float x) {
    unsigned u = __float_as_uint(x);
    return (u & 0x80000000u) ? ~u : (u | 0x80000000u);
}
__device__ __forceinline__ float dec_f(unsigned k) {
    unsigned u = (k & 0x80000000u) ? (k & 0x7fffffffu) : ~k;
    return __uint_as_float(u);
}

// split a float2 into packed fp16 hi + lo (hi = rn(v), lo = rn(v - hi))
__device__ __forceinline__ void split2(float2 v, uint32_t& hi, uint32_t& lo) {
    __half2 h2 = __float22half2_rn(v);
    float2 hf = __half22float2(h2);
    __half2 l2 = __float22half2_rn(make_float2(v.x - hf.x, v.y - hf.y));
    hi = *(uint32_t*)&h2;
    lo = *(uint32_t*)&l2;
}

// ---------------- global scratch ----------------
__device__ float g_R[128 * LSEQ * EDIM];            // r1 (0..63), r2 (64..127)
__device__ unsigned g_Su[2 * 64 * 48 * 304];        // s1 | s2 encoded max (pre-tanh)
__device__ float g_H[64 * 600];
__device__ float g_J[64 * 300];
// pre-gathered embeddings fp16 hi/lo: [s(128)][50 rows][320], pads zeroed
__device__ __half g_Xh[128 * 50 * 320];
__device__ __half g_Xl[128 * 50 * 320];
// fc0 weights, fp16 hi/lo split, layout [fc(3)][chunk(10)][n(112)][k(64)]
__device__ uint4 g_W4h[3 * 10 * 112 * 64 / 8];
__device__ uint4 g_W4l[3 * 10 * 112 * 64 / 8];
// conv weights, fp16 hi/lo, layout [t(3)][n(320)][k(320)]
__device__ __half g_CWh[3 * 320 * 320];
__device__ __half g_CWl[3 * 320 * 320];

#define S2_OFF (64 * 48 * 304)   // 933888

// ---------------------------------------------------------------------------
// prep_all: fused gather_x + init_s + prep_w + prep_cw.
// ---------------------------------------------------------------------------
#define PA_G0 128
#define PA_G1 912
#define PA_G2 210
#define PA_G3 300

__global__ __launch_bounds__(256) void prep_all(
    const int* __restrict__ q1, const int* __restrict__ q2,
    const float* __restrict__ emb, const float* __restrict__ fc0_w,
    const float* __restrict__ conv_w)
{
    int bx = blockIdx.x, tid = threadIdx.x;
    if (bx < PA_G0) {
        int s = bx;
        int b = s & 63;
        bool side = s >= 64;
        const int* q = side ? q2 : q1;
        __shared__ int toks[48];
        if (tid < 48) toks[tid] = q[b * 48 + tid];
        __syncthreads();
        size_t base = (size_t)s * 50 * 320;
        for (int idx = tid; idx < 50 * 320; idx += 256) {
            int row = idx / 320, col = idx - row * 320;
            float v = 0.f;
            if (row >= 1 && row <= 48 && col < 300)
                v = emb[(size_t)toks[row - 1] * 300 + col];
            __half h = __float2half_rn(v);
            g_Xh[base + idx] = h;
            g_Xl[base + idx] = __float2half_rn(v - __half2float(h));
        }
        return;
    }
    bx -= PA_G0;
    if (bx < PA_G1) {
        unsigned seed = ~__float_as_uint(NEGV);
        uint4 sv = make_uint4(seed, seed, seed, seed);
        unsigned base4 = (unsigned)bx * 512 + tid;
        uint4* p = (uint4*)g_Su;
        p[base4] = sv;
        p[base4 + 256] = sv;
        return;
    }
    bx -= PA_G1;
    if (bx < PA_G2) {
        for (int e = 0; e < 4; e++) {
            int idx = (bx * 1024) + tid * 4 + e;
            int fcc = idx / 7168;
            int rem = idx - fcc * 7168;
            int n = rem >> 6, k = rem & 63;
            int f = (fcc / 10) * 112 + n;
            int kg = (fcc % 10) * 64 + k;
            float v = (f < 300 && kg < 600) ? fc0_w[(size_t)f * 600 + kg] : 0.f;
            __half h = __float2half_rn(v);
            __half l = __float2half_rn(v - __half2float(h));
            size_t o = ((size_t)fcc * 112 + n) * 64 + k;
            ((__half*)g_W4h)[o] = h;
            ((__half*)g_W4l)[o] = l;
        }
        return;
    }
    bx -= PA_G2;
    {
        for (int e = 0; e < 4; e++) {
            int idx = (bx * 1024) + tid * 4 + e;
            int t = idx / 102400;
            int rem = idx - t * 102400;
            int n = rem / 320, k = rem - n * 320;
            float v = (n < 300 && k < 300) ? conv_w[(size_t)n * 900 + k * 3 + t] : 0.f;
            __half h = __float2half_rn(v);
            __half l = __float2half_rn(v - __half2float(h));
            size_t o = ((size_t)t * 320 + n) * 320 + k;
            g_CWh[o] = h;
            g_CWl[o] = l;
        }
    }
}

// ---------------------------------------------------------------------------
// encode_tc: HMMA conv1d. grid (128, 2), 192 threads. cp.async B staging.
// (R13 configuration — measured best)
// ---------------------------------------------------------------------------
#define XSTR 328
#define EBST 72
#define OF_XH 0
#define OF_XL 32800
#define OF_EBH 65600
#define OF_EBL 88640
#define SME_TOTAL 111680

__global__ __launch_bounds__(192) void encode_tc(const float* __restrict__ conv_b)
{
    int s = blockIdx.x, nh = blockIdx.y;
    extern __shared__ char smc[];
    int tid = threadIdx.x, warp = tid >> 5, lane = tid & 31;

    {
        const uint4* srch = (const uint4*)(g_Xh + (size_t)s * 16000);
        const uint4* srcl = (const uint4*)(g_Xl + (size_t)s * 16000);
        for (int i = tid; i < 50 * 40; i += 192) {
            int row = i / 40, c = i - row * 40;
            *(uint4*)(smc + OF_XH + row * (XSTR * 2) + c * 16) = srch[i];
            *(uint4*)(smc + OF_XL + row * (XSTR * 2) + c * 16) = srcl[i];
        }
    }

    int mw = warp >> 1, nw = warp & 1;
    float acc[10][4];
    #pragma unroll
    for (int n8 = 0; n8 < 10; n8++)
        #pragma unroll
        for (int v = 0; v < 4; v++) acc[n8][v] = 0.f;

    uint32_t sbase = smem_u32(smc);
    uint32_t aXh = sbase + OF_XH + (uint32_t)((mw * 16 + (lane & 15)) * XSTR + ((lane >> 4) << 3)) * 2;
    uint32_t aXl = aXh + (OF_XL - OF_XH);
    uint32_t aBh = sbase + OF_EBH + (uint32_t)((nw * 80 + (lane & 7)) * EBST + (lane & 8)) * 2;
    uint32_t aBl = aBh + (OF_EBL - OF_EBH);

    for (int t = 0; t < 3; t++) {
        const char* gwh = (const char*)(g_CWh + ((size_t)t * 320 + nh * 160) * 320);
        const char* gwl = (const char*)(g_CWl + ((size_t)t * 320 + nh * 160) * 320);
        for (int c = 0; c < 5; c++) {
            __syncthreads();
            for (int i = tid; i < 160 * 8; i += 192) {
                int n = i >> 3, kk = i & 7;
                uint32_t d = sbase + OF_EBH + (uint32_t)(n * (EBST * 2) + kk * 16);
                const size_t so = (size_t)n * 640 + c * 128 + kk * 16;
                CP_ASYNC16(d, gwh + so);
                CP_ASYNC16(d + (OF_EBL - OF_EBH), gwl + so);
            }
            CP_COMMIT();
            CP_WAIT0();
            __syncthreads();
            uint32_t aoff = (uint32_t)(t * XSTR + c * 64) * 2;
            #pragma unroll
            for (int ks = 0; ks < 4; ks++) {
                uint32_t k2 = ks * 32;
                uint32_t ah[4], al[4], bhf[10][2], blf[10][2];
                LDSM4(ah, aXh + aoff + k2);
                LDSM4(al, aXl + aoff + k2);
                #pragma unroll
                for (int n8 = 0; n8 < 10; n8++) LDSM2(bhf[n8], aBh + (uint32_t)(n8 * 8 * EBST) * 2 + k2);
                #pragma unroll
                for (int n8 = 0; n8 < 10; n8++) MMA16816(acc[n8], ah, bhf[n8]);
                #pragma unroll
                for (int n8 = 0; n8 < 10; n8++) MMA16816(acc[n8], al, bhf[n8]);
                #pragma unroll
                for (int n8 = 0; n8 < 10; n8++) LDSM2(blf[n8], aBl + (uint32_t)(n8 * 8 * EBST) * 2 + k2);
                #pragma unroll
                for (int n8 = 0; n8 < 10; n8++) MMA16816(acc[n8], ah, blf[n8]);
            }
        }
    }

    int g4 = lane >> 2, t4 = lane & 3;
    int r0 = mw * 16 + g4;
    #pragma unroll
    for (int n8 = 0; n8 < 10; n8++) {
        int eo = nh * 160 + nw * 80 + n8 * 8 + t4 * 2;
        if (eo < 300) {
            float bi = conv_b[eo];
            g_R[(size_t)(s * 48 + r0) * 300 + eo]     = tanhf(acc[n8][0] + bi);
            g_R[(size_t)(s * 48 + r0 + 8) * 300 + eo] = tanhf(acc[n8][2] + bi);
        }
        if (eo + 1 < 300) {
            float bi = conv_b[eo + 1];
            g_R[(size_t)(s * 48 + r0) * 300 + eo + 1]     = tanhf(acc[n8][1] + bi);
            g_R[(size_t)(s * 48 + r0 + 8) * 300 + eo + 1] = tanhf(acc[n8][3] + bi);
        }
    }
}

// ---------------------------------------------------------------------------
// joint_tc: single launch, NI=7, K=608, cp.async B staging, vectorized
// feature build. grid (18, 3, 64). 256 threads (8 warps 4Mx2N). (R13)
// ---------------------------------------------------------------------------
#define NI  7
#define AST 72
#define BST 72
#define JST 116
#define OF_BH 0
#define OF_BL 16384
#define OF_AH 32768
#define OF_AL 51200
#define OF_R1 69632
#define OF_R2 79360
#define SMB_TOTAL 98816

__global__ __launch_bounds__(256) void joint_tc(
    const int* __restrict__ q1_len, const int* __restrict__ q2_len)
{
    int it = blockIdx.x / 3, fc = blockIdx.x % 3;
    int jt = blockIdx.y, b = blockIdx.z;
    int l1 = q1_len[b], l2 = q2_len[b];
    if (it * 8 >= l1 || jt * 16 >= l2) return;

    extern __shared__ char smc[];
    float* r1s = (float*)(smc + OF_R1);   // [8][304]
    float* r2s = (float*)(smc + OF_R2);   // [16][304]
    float* smJ = (float*)smc;             // epilogue reuse

    int tid = threadIdx.x;
    int warp = tid >> 5, lane = tid & 31;
    int nw = warp & 1, mw = warp >> 1;
    const int NROWS = NI * 16;

    {
        const float4* R1 = (const float4*)(g_R + (size_t)(b * 48 + it * 8) * 300);
        const float4* R2 = (const float4*)(g_R + (size_t)((64 + b) * 48 + jt * 16) * 300);
        for (int i = tid; i < 8 * 75; i += 256) {
            int r = i / 75, c = i - r * 75;
            ((float4*)(r1s + r * 304))[c] = R1[r * 75 + c];
        }
        for (int i = tid; i < 16 * 75; i += 256) {
            int r = i / 75, c = i - r * 75;
            ((float4*)(r2s + r * 304))[c] = R2[r * 75 + c];
        }
    }

    float acc[2][NI][4];
    #pragma unroll
    for (int mi = 0; mi < 2; mi++)
        #pragma unroll
        for (int ni = 0; ni < NI; ni++)
            #pragma unroll
            for (int v = 0; v < 4; v++) acc[mi][ni][v] = 0.f;

    uint32_t sbase = smem_u32(smc);
    int arow = mw * 32 + (lane & 15);
    int acol = (lane >> 4) << 3;
    uint32_t aAh0 = sbase + OF_AH + (uint32_t)(arow * AST + acol) * 2;
    uint32_t aAh1 = aAh0 + 16 * AST * 2;
    uint32_t aAl0 = sbase + OF_AL + (uint32_t)(arow * AST + acol) * 2;
    uint32_t aAl1 = aAl0 + 16 * AST * 2;
    int brow = nw * (NI * 8) + (lane & 7);
    int bcol = lane & 8;
    uint32_t aBh = sbase + OF_BH + (uint32_t)(brow * BST + bcol) * 2;
    uint32_t aBl = sbase + OF_BL + (uint32_t)(brow * BST + bcol) * 2;

    int fp_ = tid >> 1, fhalf = tid & 1;
    const float2* r1p = (const float2*)(r1s + (fp_ >> 4) * 304);
    const float2* r2p = (const float2*)(r2s + (fp_ & 15) * 304);
    uint32_t* fdh = (uint32_t*)((__half*)(smc + OF_AH) + fp_ * AST + fhalf * 32);
    uint32_t* fdl = (uint32_t*)((__half*)(smc + OF_AL) + fp_ * AST + fhalf * 32);

    const char* gwh = (const char*)(g_W4h + (size_t)(fc * 10) * 896);
    const char* gwl = (const char*)(g_W4l + (size_t)(fc * 10) * 896);

#define JOINT_KSTEP(K2) do { \
        uint32_t ah[2][4], al[2][4], bh[NI][2], bl[NI][2]; \
        LDSM4(ah[0], aAh0 + (K2)); \
        LDSM4(ah[1], aAh1 + (K2)); \
        _Pragma("unroll") \
        for (int n8 = 0; n8 < NI; n8++) LDSM2(bh[n8], aBh + (uint32_t)(n8 * 8 * BST) * 2 + (K2)); \
        _Pragma("unroll") \
        for (int mi = 0; mi < 2; mi++) \
            _Pragma("unroll") \
            for (int ni = 0; ni < NI; ni++) MMA16816(acc[mi][ni], ah[mi], bh[ni]); \
        LDSM4(al[0], aAl0 + (K2)); \
        LDSM4(al[1], aAl1 + (K2)); \
        _Pragma("unroll") \
        for (int mi = 0; mi < 2; mi++) \
            _Pragma("unroll") \
            for (int ni = 0; ni < NI; ni++) MMA16816(acc[mi][ni], al[mi], bh[ni]); \
        _Pragma("unroll") \
        for (int n8 = 0; n8 < NI; n8++) LDSM2(bl[n8], aBl + (uint32_t)(n8 * 8 * BST) * 2 + (K2)); \
        _Pragma("unroll") \
        for (int mi = 0; mi < 2; mi++) \
            _Pragma("unroll") \
            for (int ni = 0; ni < NI; ni++) MMA16816(acc[mi][ni], ah[mi], bl[ni]); \
    } while (0)

    for (int c = 0; c < 10; c++) {
        __syncthreads();
        {
            const char* sh = gwh + (size_t)c * 896 * 16;
            const char* sl = gwl + (size_t)c * 896 * 16;
            for (int i = tid; i < NROWS * 8; i += 256) {
                int n = i >> 3, kk = i & 7;
                uint32_t d = sbase + OF_BH + (uint32_t)(n * (BST * 2) + kk * 16);
                CP_ASYNC16(d, sh + i * 16);
                CP_ASYNC16(d + (OF_BL - OF_BH), sl + i * 16);
            }
            CP_COMMIT();
        }
        if (c < 9 || fhalf == 0) {
            int kb2 = (c * 64 + fhalf * 32) >> 1;
            if (c < 4 || (c == 4 && fhalf == 0)) {
                #pragma unroll
                for (int m = 0; m < 16; m++) {
                    float2 a = r1p[kb2 + m], bb = r2p[kb2 + m];
                    uint32_t hi, lo;
                    split2(make_float2(fabsf(a.x - bb.x), fabsf(a.y - bb.y)), hi, lo);
                    fdh[m] = hi; fdl[m] = lo;
                }
            } else if (c >= 5) {
                int kp2 = kb2 - 150;
                #pragma unroll
                for (int m = 0; m < 16; m++) {
                    bool valid = (kp2 + m) < 150;  // e < 600 (c==9 tail)
                    int idx = valid ? (kp2 + m) : 0;
                    float2 a = r1p[idx], bb = r2p[idx];
                    uint32_t hi, lo;
                    split2(make_float2(a.x * bb.x, a.y * bb.y), hi, lo);
                    fdh[m] = valid ? hi : 0u;
                    fdl[m] = valid ? lo : 0u;
                }
            } else {
                #pragma unroll
                for (int m = 0; m < 16; m++) {
                    int e = (kb2 + m) * 2;
                    const float* r1f = (const float*)r1p;
                    const float* r2f = (const float*)r2p;
                    float v0, v1;
                    if (e < 300)      { v0 = fabsf(r1f[e] - r2f[e]);     v1 = (e + 1 < 300) ? fabsf(r1f[e + 1] - r2f[e + 1]) : r1f[e + 1 - 300] * r2f[e + 1 - 300]; }
                    else              { v0 = r1f[e - 300] * r2f[e - 300]; v1 = r1f[e - 299] * r2f[e - 299]; }
                    uint32_t hi, lo;
                    split2(make_float2(v0, v1), hi, lo);
                    fdh[m] = hi; fdl[m] = lo;
                }
            }
        }
        CP_WAIT0();
        __syncthreads();

        if (c < 9) {
            #pragma unroll
            for (int ks = 0; ks < 4; ks++) JOINT_KSTEP((uint32_t)(ks * 16) * 2);
        } else {
            JOINT_KSTEP(0u);
            JOINT_KSTEP((uint32_t)(16 * 2));
        }
    }
#undef JOINT_KSTEP
    __syncthreads();

    {
        int r0 = mw * 32 + (lane >> 2);
        int c0 = nw * (NI * 8) + (lane & 3) * 2;
        #pragma unroll
        for (int mi = 0; mi < 2; mi++)
            #pragma unroll
            for (int ni = 0; ni < NI; ni++) {
                int r = r0 + mi * 16, cc = c0 + ni * 8;
                smJ[r * JST + cc]           = acc[mi][ni][0];
                smJ[r * JST + cc + 1]       = acc[mi][ni][1];
                smJ[(r + 8) * JST + cc]     = acc[mi][ni][2];
                smJ[(r + 8) * JST + cc + 1] = acc[mi][ni][3];
            }
    }
    __syncthreads();

    int fbase = fc * 112;
    int flim = (fc == 2) ? 76 : 112;
    int icnt = min(8, l1 - it * 8);
    int jcnt = min(16, l2 - jt * 16);

    for (int idx = tid; idx < icnt * flim; idx += 256) {
        int i = idx / flim, f = idx - i * flim;
        float v = smJ[(i * 16) * JST + f];
        for (int j = 1; j < jcnt; j++) v = fmaxf(v, smJ[(i * 16 + j) * JST + f]);
        int ig = it * 8 + i, fg = fbase + f;
        atomicMax(&g_Su[(size_t)(b * 48 + ig) * 304 + fg], enc_f(v));
    }
    for (int idx = tid; idx < jcnt * flim; idx += 256) {
        int j = idx / flim, f = idx - j * flim;
        float v = smJ[j * JST + f];
        for (int i = 1; i < icnt; i++) v = fmaxf(v, smJ[(i * 16 + j) * JST + f]);
        int jg = jt * 16 + j, fg = fbase + f;
        atomicMax(&g_Su[S2_OFF + (size_t)(b * 48 + jg) * 304 + fg], enc_f(v));
    }
}

// ---------------------------------------------------------------------------
// pool: decode s + tanh+bias ; attention softmax ; h -> g_H
// grid (2, 64), 512 threads (R14 — measured 16.8us).
// ---------------------------------------------------------------------------
__global__ __launch_bounds__(512) void pool_kernel(
    const int* __restrict__ q1_len, const int* __restrict__ q2_len,
    const float* __restrict__ att_w, const float* __restrict__ att_b,
    const float* __restrict__ fc0_b)
{
    int side = blockIdx.x, b = blockIdx.y;
    int l1 = q1_len[b], l2 = q2_len[b];
    int len = side ? l2 : l1;
    const unsigned* Sb = g_Su + (size_t)side * S2_OFF + (size_t)b * 48 * 304;

    extern __shared__ float sm[];
    float* sv = sm;              // [48][301]
    float* lg = sv + 48 * 301;   // [48]
    int tid = threadIdx.x;

    for (int idx = tid; idx < len * 300; idx += 512) {
        int l = idx / 300, f = idx - l * 300;
        sv[l * 301 + f] = tanhf(dec_f(Sb[(size_t)l * 304 + f]) + fc0_b[f]);
    }
    __syncthreads();

    int lane = tid & 31, warp = tid >> 5;
    const float* Rbase = g_R + (size_t)(side * 64 + b) * 48 * 300;
    for (int l = warp; l < len; l += 16) {
        float a = 0.f;
        for (int e = lane; e < 300; e += 32) {
            a += att_w[e]       * Rbase[l * 300 + e];
            a += att_w[300 + e] * sv[l * 301 + e];
        }
        #pragma unroll
        for (int d = 16; d; d >>= 1) a += __shfl_xor_sync(0xffffffffu, a, d);
        if (lane == 0) lg[l] = a + att_b[0];
    }
    __syncthreads();

    if (warp == 0) {
        float v0 = (lane < len) ? lg[lane] : NEGV;
        float v1 = (lane + 32 < len) ? lg[lane + 32] : NEGV;
        float mx = fmaxf(v0, v1);
        #pragma unroll
        for (int d = 16; d; d >>= 1) mx = fmaxf(mx, __shfl_xor_sync(0xffffffffu, mx, d));
        float e0 = (lane < len) ? expf(v0 - mx) : 0.f;
        float e1 = (lane + 32 < len) ? expf(v1 - mx) : 0.f;
        float s = e0 + e1;
        #pragma unroll
        for (int d = 16; d; d >>= 1) s += __shfl_xor_sync(0xffffffffu, s, d);
        float inv = 1.f / s;
        if (lane < len) lg[lane] = e0 * inv;
        if (lane + 32 < len) lg[lane + 32] = e1 * inv;
    }
    __syncthreads();

    for (int f = tid; f < 300; f += 512) {
        float h = 0.f;
        for (int l = 0; l < len; l++) h += lg[l] * sv[l * 301 + f];
        g_H[b * 600 + side * 300 + f] = h;
    }
}

// ---------------------------------------------------------------------------
// head1: jv = tanh(H @ fc1_w^T + b). grid (64, 5), block 256.
// ---------------------------------------------------------------------------
__global__ __launch_bounds__(256) void head1_kernel(
    const float* __restrict__ fc1_w, const float* __restrict__ fc1_b)
{
    __shared__ float Hs[600];
    __shared__ float part[256];
    int b = blockIdx.x, fb = blockIdx.y;
    int tid = threadIdx.x;
    for (int i = tid; i < 600; i += 256) Hs[i] = g_H[b * 600 + i];
    __syncthreads();
    int fl = tid >> 2, seg = tid & 3;
    int f = fb * 60 + fl;
    float acc = 0.f;
    if (fl < 60) {
        const float* w = fc1_w + (size_t)f * 600 + seg * 150;
        const float* h = Hs + seg * 150;
        #pragma unroll 6
        for (int k = 0; k < 150; k++) acc += h[k] * w[k];
    }
    part[tid] = acc;
    __syncthreads();
    if (seg == 0 && fl < 60) {
        float s = part[tid] + part[tid + 1] + part[tid + 2] + part[tid + 3];
        g_J[b * 300 + f] = tanhf(s + fc1_b[f]);
    }
}

// head2: out = jv @ fc2_w^T + b. grid 64, block 64.
__global__ __launch_bounds__(64) void head2_kernel(
    const float* __restrict__ fc2_w, const float* __restrict__ fc2_b,
    float* __restrict__ out)
{
    int b = blockIdx.x, tid = threadIdx.x;
    int c = tid >> 5, lane = tid & 31;
    float acc = 0.f;
    for (int f = lane; f < 300; f += 32)
        acc += g_J[b * 300 + f] * fc2_w[c * 300 + f];
    #pragma unroll
    for (int d = 16; d; d >>= 1) acc += __shfl_xor_sync(0xffffffffu, acc, d);
    if (lane == 0) out[b * 2 + c] = acc + fc2_b[c];
}

// ---------------------------------------------------------------------------
extern "C" void kernel_launch(void* const* d_in, const int* in_sizes, int n_in,
                              void* d_out, int out_size)
{
    const int*   q1     = (const int*)d_in[0];
    const int*   q2     = (const int*)d_in[1];
    const int*   q1_len = (const int*)d_in[2];
    const int*   q2_len = (const int*)d_in[3];
    const float* emb    = (const float*)d_in[4];
    const float* conv_w = (const float*)d_in[5];
    const float* conv_b = (const float*)d_in[6];
    const float* fc0_w  = (const float*)d_in[7];
    const float* fc0_b  = (const float*)d_in[8];
    const float* fc1_w  = (const float*)d_in[9];
    const float* fc1_b  = (const float*)d_in[10];
    const float* fc2_w  = (const float*)d_in[11];
    const float* fc2_b  = (const float*)d_in[12];
    const float* att_w  = (const float*)d_in[13];
    const float* att_b  = (const float*)d_in[14];
    float* out = (float*)d_out;

    const int smC = 48 * 301 * 4 + 48 * 4;

    cudaFuncSetAttribute(encode_tc,   cudaFuncAttributeMaxDynamicSharedMemorySize, SME_TOTAL);
    cudaFuncSetAttribute(joint_tc,    cudaFuncAttributeMaxDynamicSharedMemorySize, SMB_TOTAL);
    cudaFuncSetAttribute(pool_kernel, cudaFuncAttributeMaxDynamicSharedMemorySize, smC);

    prep_all<<<PA_G0 + PA_G1 + PA_G2 + PA_G3, 256>>>(q1, q2, emb, fc0_w, conv_w);
    encode_tc<<<dim3(128, 2), 192, SME_TOTAL>>>(conv_b);
    joint_tc<<<dim3(18, 3, 64), 256, SMB_TOTAL>>>(q1_len, q2_len);
    pool_kernel<<<dim3(2, 64), 512, smC>>>(q1_len, q2_len, att_w, att_b, fc0_b);
    head1_kernel<<<dim3(64, 5), 256>>>(fc1_w, fc1_b);
    head2_kernel<<<64, 64>>>(fc2_w, fc2_b, out);
    (void)in_sizes; (void)n_in; (void)out_size;
}

// round 17
// speedup vs baseline: 1.1675x; 1.1369x over previous
#include <cuda_runtime.h>
#include <cuda_fp16.h>
#include <cstdint>
#include <math.h>

#define BATCH 64
#define LSEQ  48
#define EDIM  300
#define F0DIM 300
#define NEGV  (-1000000000.0f)

// ---------------- helpers ----------------
__device__ __forceinline__ uint32_t smem_u32(const void* p) {
    uint32_t a;
    asm("{ .reg .u64 t; cvta.to.shared.u64 t, %1; cvt.u32.u64 %0, t; }"
        : "=r"(a) : "l"(p));
    return a;
}
#define LDSM4(r, addr) \
    asm volatile("ldmatrix.sync.aligned.m8n8.x4.shared.b16 {%0,%1,%2,%3}, [%4];" \
        : "=r"((r)[0]), "=r"((r)[1]), "=r"((r)[2]), "=r"((r)[3]) : "r"(addr))
#define LDSM2(r, addr) \
    asm volatile("ldmatrix.sync.aligned.m8n8.x2.shared.b16 {%0,%1}, [%2];" \
        : "=r"((r)[0]), "=r"((r)[1]) : "r"(addr))
#define MMA16816(c, a, bb) \
    asm volatile("mma.sync.aligned.m16n8k16.row.col.f32.f16.f16.f32 " \
        "{%0,%1,%2,%3}, {%4,%5,%6,%7}, {%8,%9}, {%0,%1,%2,%3};" \
        : "+f"((c)[0]), "+f"((c)[1]), "+f"((c)[2]), "+f"((c)[3]) \
        : "r"((a)[0]), "r"((a)[1]), "r"((a)[2]), "r"((a)[3]), \
          "r"((bb)[0]), "r"((bb)[1]))
#define CP_ASYNC16(dst, src) \
    asm volatile("cp.async.cg.shared.global [%0], [%1], 16;" :: "r"(dst), "l"(src))
#define CP_COMMIT() asm volatile("cp.async.commit_group;" ::: "memory")
#define CP_WAIT0()  asm volatile("cp.async.wait_group 0;" ::: "memory")

// order-preserving float<->uint for atomic max
__device__ __forceinline__ unsigned enc_f(float x) {
    unsigned u = __float_as_uint(x);
    return (u & 0x80000000u) ? ~u : (u | 0x80000000u);
}
__device__ __forceinline__ float dec_f(unsigned k) {
    unsigned u = (k & 0x80000000u) ? (k & 0x7fffffffu) : ~k;
    return __uint_as_float(u);
}

// hi-only pack
__device__ __forceinline__ uint32_t pack2(float2 v) {
    __half2 h2 = __float22half2_rn(v);
    return *(uint32_t*)&h2;
}

// ---------------- global scratch ----------------
__device__ float g_R[128 * LSEQ * EDIM];            // r1 (0..63), r2 (64..127)
__device__ unsigned g_Su[2 * 64 * 48 * 304];        // s1 | s2 encoded max (pre-tanh)
__device__ float g_H[64 * 600];
__device__ float g_J[64 * 300];
// pre-gathered embeddings fp16 hi/lo: [s(128)][50 rows][320], pads zeroed
__device__ __half g_Xh[128 * 50 * 320];
__device__ __half g_Xl[128 * 50 * 320];
// fc0 weights, fp16 hi/lo split, layout [fc(3)][chunk(10)][n(112)][k(64)]
__device__ uint4 g_W4h[3 * 10 * 112 * 64 / 8];
__device__ uint4 g_W4l[3 * 10 * 112 * 64 / 8];
// conv weights, fp16 hi/lo, layout [t(3)][n(320)][k(320)]
__device__ __half g_CWh[3 * 320 * 320];
__device__ __half g_CWl[3 * 320 * 320];

#define S2_OFF (64 * 48 * 304)   // 933888

// ---------------------------------------------------------------------------
// prep_all: fused gather_x + init_s + prep_w + prep_cw.
// ---------------------------------------------------------------------------
#define PA_G0 128
#define PA_G1 912
#define PA_G2 210
#define PA_G3 300

__global__ __launch_bounds__(256) void prep_all(
    const int* __restrict__ q1, const int* __restrict__ q2,
    const float* __restrict__ emb, const float* __restrict__ fc0_w,
    const float* __restrict__ conv_w)
{
    int bx = blockIdx.x, tid = threadIdx.x;
    if (bx < PA_G0) {
        int s = bx;
        int b = s & 63;
        bool side = s >= 64;
        const int* q = side ? q2 : q1;
        __shared__ int toks[48];
        if (tid < 48) toks[tid] = q[b * 48 + tid];
        __syncthreads();
        size_t base = (size_t)s * 50 * 320;
        for (int idx = tid; idx < 50 * 320; idx += 256) {
            int row = idx / 320, col = idx - row * 320;
            float v = 0.f;
            if (row >= 1 && row <= 48 && col < 300)
                v = emb[(size_t)toks[row - 1] * 300 + col];
            __half h = __float2half_rn(v);
            g_Xh[base + idx] = h;
            g_Xl[base + idx] = __float2half_rn(v - __half2float(h));
        }
        return;
    }
    bx -= PA_G0;
    if (bx < PA_G1) {
        unsigned seed = ~__float_as_uint(NEGV);
        uint4 sv = make_uint4(seed, seed, seed, seed);
        unsigned base4 = (unsigned)bx * 512 + tid;
        uint4* p = (uint4*)g_Su;
        p[base4] = sv;
        p[base4 + 256] = sv;
        return;
    }
    bx -= PA_G1;
    if (bx < PA_G2) {
        for (int e = 0; e < 4; e++) {
            int idx = (bx * 1024) + tid * 4 + e;
            int fcc = idx / 7168;
            int rem = idx - fcc * 7168;
            int n = rem >> 6, k = rem & 63;
            int f = (fcc / 10) * 112 + n;
            int kg = (fcc % 10) * 64 + k;
            float v = (f < 300 && kg < 600) ? fc0_w[(size_t)f * 600 + kg] : 0.f;
            __half h = __float2half_rn(v);
            __half l = __float2half_rn(v - __half2float(h));
            size_t o = ((size_t)fcc * 112 + n) * 64 + k;
            ((__half*)g_W4h)[o] = h;
            ((__half*)g_W4l)[o] = l;
        }
        return;
    }
    bx -= PA_G2;
    {
        for (int e = 0; e < 4; e++) {
            int idx = (bx * 1024) + tid * 4 + e;
            int t = idx / 102400;
            int rem = idx - t * 102400;
            int n = rem / 320, k = rem - n * 320;
            float v = (n < 300 && k < 300) ? conv_w[(size_t)n * 900 + k * 3 + t] : 0.f;
            __half h = __float2half_rn(v);
            __half l = __float2half_rn(v - __half2float(h));
            size_t o = ((size_t)t * 320 + n) * 320 + k;
            g_CWh[o] = h;
            g_CWl[o] = l;
        }
    }
}

// ---------------------------------------------------------------------------
// encode_tc: HMMA conv1d. grid (128, 2), 192 threads. cp.async B staging.
// 3-term split kept.
// ---------------------------------------------------------------------------
#define XSTR 328
#define EBST 72
#define OF_XH 0
#define OF_XL 32800
#define OF_EBH 65600
#define OF_EBL 88640
#define SME_TOTAL 111680

__global__ __launch_bounds__(192) void encode_tc(const float* __restrict__ conv_b)
{
    int s = blockIdx.x, nh = blockIdx.y;
    extern __shared__ char smc[];
    int tid = threadIdx.x, warp = tid >> 5, lane = tid & 31;

    {
        const uint4* srch = (const uint4*)(g_Xh + (size_t)s * 16000);
        const uint4* srcl = (const uint4*)(g_Xl + (size_t)s * 16000);
        for (int i = tid; i < 50 * 40; i += 192) {
            int row = i / 40, c = i - row * 40;
            *(uint4*)(smc + OF_XH + row * (XSTR * 2) + c * 16) = srch[i];
            *(uint4*)(smc + OF_XL + row * (XSTR * 2) + c * 16) = srcl[i];
        }
    }

    int mw = warp >> 1, nw = warp & 1;
    float acc[10][4];
    #pragma unroll
    for (int n8 = 0; n8 < 10; n8++)
        #pragma unroll
        for (int v = 0; v < 4; v++) acc[n8][v] = 0.f;

    uint32_t sbase = smem_u32(smc);
    uint32_t aXh = sbase + OF_XH + (uint32_t)((mw * 16 + (lane & 15)) * XSTR + ((lane >> 4) << 3)) * 2;
    uint32_t aXl = aXh + (OF_XL - OF_XH);
    uint32_t aBh = sbase + OF_EBH + (uint32_t)((nw * 80 + (lane & 7)) * EBST + (lane & 8)) * 2;
    uint32_t aBl = aBh + (OF_EBL - OF_EBH);

    for (int t = 0; t < 3; t++) {
        const char* gwh = (const char*)(g_CWh + ((size_t)t * 320 + nh * 160) * 320);
        const char* gwl = (const char*)(g_CWl + ((size_t)t * 320 + nh * 160) * 320);
        for (int c = 0; c < 5; c++) {
            __syncthreads();
            for (int i = tid; i < 160 * 8; i += 192) {
                int n = i >> 3, kk = i & 7;
                uint32_t d = sbase + OF_EBH + (uint32_t)(n * (EBST * 2) + kk * 16);
                const size_t so = (size_t)n * 640 + c * 128 + kk * 16;
                CP_ASYNC16(d, gwh + so);
                CP_ASYNC16(d + (OF_EBL - OF_EBH), gwl + so);
            }
            CP_COMMIT();
            CP_WAIT0();
            __syncthreads();
            uint32_t aoff = (uint32_t)(t * XSTR + c * 64) * 2;
            #pragma unroll
            for (int ks = 0; ks < 4; ks++) {
                uint32_t k2 = ks * 32;
                uint32_t ah[4], al[4], bhf[10][2], blf[10][2];
                LDSM4(ah, aXh + aoff + k2);
                LDSM4(al, aXl + aoff + k2);
                #pragma unroll
                for (int n8 = 0; n8 < 10; n8++) LDSM2(bhf[n8], aBh + (uint32_t)(n8 * 8 * EBST) * 2 + k2);
                #pragma unroll
                for (int n8 = 0; n8 < 10; n8++) MMA16816(acc[n8], ah, bhf[n8]);
                #pragma unroll
                for (int n8 = 0; n8 < 10; n8++) MMA16816(acc[n8], al, bhf[n8]);
                #pragma unroll
                for (int n8 = 0; n8 < 10; n8++) LDSM2(blf[n8], aBl + (uint32_t)(n8 * 8 * EBST) * 2 + k2);
                #pragma unroll
                for (int n8 = 0; n8 < 10; n8++) MMA16816(acc[n8], ah, blf[n8]);
            }
        }
    }

    int g4 = lane >> 2, t4 = lane & 3;
    int r0 = mw * 16 + g4;
    #pragma unroll
    for (int n8 = 0; n8 < 10; n8++) {
        int eo = nh * 160 + nw * 80 + n8 * 8 + t4 * 2;
        if (eo < 300) {
            float bi = conv_b[eo];
            g_R[(size_t)(s * 48 + r0) * 300 + eo]     = tanhf(acc[n8][0] + bi);
            g_R[(size_t)(s * 48 + r0 + 8) * 300 + eo] = tanhf(acc[n8][2] + bi);
        }
        if (eo + 1 < 300) {
            float bi = conv_b[eo + 1];
            g_R[(size_t)(s * 48 + r0) * 300 + eo + 1]     = tanhf(acc[n8][1] + bi);
            g_R[(size_t)(s * 48 + r0 + 8) * 300 + eo + 1] = tanhf(acc[n8][3] + bi);
        }
    }
}

// ---------------------------------------------------------------------------
// joint_tc: 2-TERM split (Ahi*Bhi + Ahi*Blo). NI=7, K=608, cp.async B staging.
// grid (18, 3, 64). 256 threads (8 warps 4Mx2N). smem 80.4 KB (2 CTAs/SM).
// FIX R16: SMB_TOTAL now includes full 16-row r2 tile (was undersized).
// ---------------------------------------------------------------------------
#define NI  7
#define AST 72
#define BST 72
#define JST 116
#define OF_BH 0
#define OF_BL 16384
#define OF_AH 32768
#define OF_R1 51200
#define OF_R2 60928
#define SMB_TOTAL 80384

__global__ __launch_bounds__(256) void joint_tc(
    const int* __restrict__ q1_len, const int* __restrict__ q2_len)
{
    int it = blockIdx.x / 3, fc = blockIdx.x % 3;
    int jt = blockIdx.y, b = blockIdx.z;
    int l1 = q1_len[b], l2 = q2_len[b];
    if (it * 8 >= l1 || jt * 16 >= l2) return;

    extern __shared__ char smc[];
    float* r1s = (float*)(smc + OF_R1);   // [8][304]
    float* r2s = (float*)(smc + OF_R2);   // [16][304]
    float* smJ = (float*)smc;             // epilogue reuse

    int tid = threadIdx.x;
    int warp = tid >> 5, lane = tid & 31;
    int nw = warp & 1, mw = warp >> 1;
    const int NROWS = NI * 16;

    {
        const float4* R1 = (const float4*)(g_R + (size_t)(b * 48 + it * 8) * 300);
        const float4* R2 = (const float4*)(g_R + (size_t)((64 + b) * 48 + jt * 16) * 300);
        for (int i = tid; i < 8 * 75; i += 256) {
            int r = i / 75, c = i - r * 75;
            ((float4*)(r1s + r * 304))[c] = R1[r * 75 + c];
        }
        for (int i = tid; i < 16 * 75; i += 256) {
            int r = i / 75, c = i - r * 75;
            ((float4*)(r2s + r * 304))[c] = R2[r * 75 + c];
        }
    }

    float acc[2][NI][4];
    #pragma unroll
    for (int mi = 0; mi < 2; mi++)
        #pragma unroll
        for (int ni = 0; ni < NI; ni++)
            #pragma unroll
            for (int v = 0; v < 4; v++) acc[mi][ni][v] = 0.f;

    uint32_t sbase = smem_u32(smc);
    int arow = mw * 32 + (lane & 15);
    int acol = (lane >> 4) << 3;
    uint32_t aAh0 = sbase + OF_AH + (uint32_t)(arow * AST + acol) * 2;
    uint32_t aAh1 = aAh0 + 16 * AST * 2;
    int brow = nw * (NI * 8) + (lane & 7);
    int bcol = lane & 8;
    uint32_t aBh = sbase + OF_BH + (uint32_t)(brow * BST + bcol) * 2;
    uint32_t aBl = sbase + OF_BL + (uint32_t)(brow * BST + bcol) * 2;

    int fp_ = tid >> 1, fhalf = tid & 1;
    const float2* r1p = (const float2*)(r1s + (fp_ >> 4) * 304);
    const float2* r2p = (const float2*)(r2s + (fp_ & 15) * 304);
    uint32_t* fdh = (uint32_t*)((__half*)(smc + OF_AH) + fp_ * AST + fhalf * 32);

    const char* gwh = (const char*)(g_W4h + (size_t)(fc * 10) * 896);
    const char* gwl = (const char*)(g_W4l + (size_t)(fc * 10) * 896);

#define JOINT_KSTEP(K2) do { \
        uint32_t ah[2][4], bh[NI][2], bl[NI][2]; \
        LDSM4(ah[0], aAh0 + (K2)); \
        LDSM4(ah[1], aAh1 + (K2)); \
        _Pragma("unroll") \
        for (int n8 = 0; n8 < NI; n8++) LDSM2(bh[n8], aBh + (uint32_t)(n8 * 8 * BST) * 2 + (K2)); \
        _Pragma("unroll") \
        for (int mi = 0; mi < 2; mi++) \
            _Pragma("unroll") \
            for (int ni = 0; ni < NI; ni++) MMA16816(acc[mi][ni], ah[mi], bh[ni]); \
        _Pragma("unroll") \
        for (int n8 = 0; n8 < NI; n8++) LDSM2(bl[n8], aBl + (uint32_t)(n8 * 8 * BST) * 2 + (K2)); \
        _Pragma("unroll") \
        for (int mi = 0; mi < 2; mi++) \
            _Pragma("unroll") \
            for (int ni = 0; ni < NI; ni++) MMA16816(acc[mi][ni], ah[mi], bl[ni]); \
    } while (0)

    for (int c = 0; c < 10; c++) {
        __syncthreads();
        {
            const char* sh = gwh + (size_t)c * 896 * 16;
            const char* sl = gwl + (size_t)c * 896 * 16;
            for (int i = tid; i < NROWS * 8; i += 256) {
                int n = i >> 3, kk = i & 7;
                uint32_t d = sbase + OF_BH + (uint32_t)(n * (BST * 2) + kk * 16);
                CP_ASYNC16(d, sh + i * 16);
                CP_ASYNC16(d + (OF_BL - OF_BH), sl + i * 16);
            }
            CP_COMMIT();
        }
        // feature build (hi only): 16 float2 pairs per thread per chunk
        if (c < 9 || fhalf == 0) {
            int kb2 = (c * 64 + fhalf * 32) >> 1;
            if (c < 4 || (c == 4 && fhalf == 0)) {
                #pragma unroll
                for (int m = 0; m < 16; m++) {
                    float2 a = r1p[kb2 + m], bb = r2p[kb2 + m];
                    fdh[m] = pack2(make_float2(fabsf(a.x - bb.x), fabsf(a.y - bb.y)));
                }
            } else if (c >= 5) {
                int kp2 = kb2 - 150;
                #pragma unroll
                for (int m = 0; m < 16; m++) {
                    bool valid = (kp2 + m) < 150;  // e < 600 (c==9 tail)
                    int idx = valid ? (kp2 + m) : 0;
                    float2 a = r1p[idx], bb = r2p[idx];
                    uint32_t hi = pack2(make_float2(a.x * bb.x, a.y * bb.y));
                    fdh[m] = valid ? hi : 0u;
                }
            } else {
                #pragma unroll
                for (int m = 0; m < 16; m++) {
                    int e = (kb2 + m) * 2;
                    const float* r1f = (const float*)r1p;
                    const float* r2f = (const float*)r2p;
                    float v0, v1;
                    if (e < 300)      { v0 = fabsf(r1f[e] - r2f[e]);     v1 = (e + 1 < 300) ? fabsf(r1f[e + 1] - r2f[e + 1]) : r1f[e + 1 - 300] * r2f[e + 1 - 300]; }
                    else              { v0 = r1f[e - 300] * r2f[e - 300]; v1 = r1f[e - 299] * r2f[e - 299]; }
                    fdh[m] = pack2(make_float2(v0, v1));
                }
            }
        }
        CP_WAIT0();
        __syncthreads();

        if (c < 9) {
            #pragma unroll
            for (int ks = 0; ks < 4; ks++) JOINT_KSTEP((uint32_t)(ks * 16) * 2);
        } else {
            JOINT_KSTEP(0u);
            JOINT_KSTEP((uint32_t)(16 * 2));
        }
    }
#undef JOINT_KSTEP
    __syncthreads();

    {
        int r0 = mw * 32 + (lane >> 2);
        int c0 = nw * (NI * 8) + (lane & 3) * 2;
        #pragma unroll
        for (int mi = 0; mi < 2; mi++)
            #pragma unroll
            for (int ni = 0; ni < NI; ni++) {
                int r = r0 + mi * 16, cc = c0 + ni * 8;
                smJ[r * JST + cc]           = acc[mi][ni][0];
                smJ[r * JST + cc + 1]       = acc[mi][ni][1];
                smJ[(r + 8) * JST + cc]     = acc[mi][ni][2];
                smJ[(r + 8) * JST + cc + 1] = acc[mi][ni][3];
            }
    }
    __syncthreads();

    int fbase = fc * 112;
    int flim = (fc == 2) ? 76 : 112;
    int icnt = min(8, l1 - it * 8);
    int jcnt = min(16, l2 - jt * 16);

    for (int idx = tid; idx < icnt * flim; idx += 256) {
        int i = idx / flim, f = idx - i * flim;
        float v = smJ[(i * 16) * JST + f];
        for (int j = 1; j < jcnt; j++) v = fmaxf(v, smJ[(i * 16 + j) * JST + f]);
        int ig = it * 8 + i, fg = fbase + f;
        atomicMax(&g_Su[(size_t)(b * 48 + ig) * 304 + fg], enc_f(v));
    }
    for (int idx = tid; idx < jcnt * flim; idx += 256) {
        int j = idx / flim, f = idx - j * flim;
        float v = smJ[j * JST + f];
        for (int i = 1; i < icnt; i++) v = fmaxf(v, smJ[(i * 16 + j) * JST + f]);
        int jg = jt * 16 + j, fg = fbase + f;
        atomicMax(&g_Su[S2_OFF + (size_t)(b * 48 + jg) * 304 + fg], enc_f(v));
    }
}

// ---------------------------------------------------------------------------
// pool: decode s + tanh+bias ; attention softmax ; h -> g_H
// grid (2, 64), 512 threads.
// ---------------------------------------------------------------------------
__global__ __launch_bounds__(512) void pool_kernel(
    const int* __restrict__ q1_len, const int* __restrict__ q2_len,
    const float* __restrict__ att_w, const float* __restrict__ att_b,
    const float* __restrict__ fc0_b)
{
    int side = blockIdx.x, b = blockIdx.y;
    int l1 = q1_len[b], l2 = q2_len[b];
    int len = side ? l2 : l1;
    const unsigned* Sb = g_Su + (size_t)side * S2_OFF + (size_t)b * 48 * 304;

    extern __shared__ float sm[];
    float* sv = sm;              // [48][301]
    float* lg = sv + 48 * 301;   // [48]
    int tid = threadIdx.x;

    for (int idx = tid; idx < len * 300; idx += 512) {
        int l = idx / 300, f = idx - l * 300;
        sv[l * 301 + f] = tanhf(dec_f(Sb[(size_t)l * 304 + f]) + fc0_b[f]);
    }
    __syncthreads();

    int lane = tid & 31, warp = tid >> 5;
    const float* Rbase = g_R + (size_t)(side * 64 + b) * 48 * 300;
    for (int l = warp; l < len; l += 16) {
        float a = 0.f;
        for (int e = lane; e < 300; e += 32) {
            a += att_w[e]       * Rbase[l * 300 + e];
            a += att_w[300 + e] * sv[l * 301 + e];
        }
        #pragma unroll
        for (int d = 16; d; d >>= 1) a += __shfl_xor_sync(0xffffffffu, a, d);
        if (lane == 0) lg[l] = a + att_b[0];
    }
    __syncthreads();

    if (warp == 0) {
        float v0 = (lane < len) ? lg[lane] : NEGV;
        float v1 = (lane + 32 < len) ? lg[lane + 32] : NEGV;
        float mx = fmaxf(v0, v1);
        #pragma unroll
        for (int d = 16; d; d >>= 1) mx = fmaxf(mx, __shfl_xor_sync(0xffffffffu, mx, d));
        float e0 = (lane < len) ? expf(v0 - mx) : 0.f;
        float e1 = (lane + 32 < len) ? expf(v1 - mx) : 0.f;
        float s = e0 + e1;
        #pragma unroll
        for (int d = 16; d; d >>= 1) s += __shfl_xor_sync(0xffffffffu, s, d);
        float inv = 1.f / s;
        if (lane < len) lg[lane] = e0 * inv;
        if (lane + 32 < len) lg[lane + 32] = e1 * inv;
    }
    __syncthreads();

    for (int f = tid; f < 300; f += 512) {
        float h = 0.f;
        for (int l = 0; l < len; l++) h += lg[l] * sv[l * 301 + f];
        g_H[b * 600 + side * 300 + f] = h;
    }
}

// ---------------------------------------------------------------------------
// head1: jv = tanh(H @ fc1_w^T + b). grid (64, 5), block 256.
// ---------------------------------------------------------------------------
__global__ __launch_bounds__(256) void head1_kernel(
    const float* __restrict__ fc1_w, const float* __restrict__ fc1_b)
{
    __shared__ float Hs[600];
    __shared__ float part[256];
    int b = blockIdx.x, fb = blockIdx.y;
    int tid = threadIdx.x;
    for (int i = tid; i < 600; i += 256) Hs[i] = g_H[b * 600 + i];
    __syncthreads();
    int fl = tid >> 2, seg = tid & 3;
    int f = fb * 60 + fl;
    float acc = 0.f;
    if (fl < 60) {
        const float* w = fc1_w + (size_t)f * 600 + seg * 150;
        const float* h = Hs + seg * 150;
        #pragma unroll 6
        for (int k = 0; k < 150; k++) acc += h[k] * w[k];
    }
    part[tid] = acc;
    __syncthreads();
    if (seg == 0 && fl < 60) {
        float s = part[tid] + part[tid + 1] + part[tid + 2] + part[tid + 3];
        g_J[b * 300 + f] = tanhf(s + fc1_b[f]);
    }
}

// head2: out = jv @ fc2_w^T + b. grid 64, block 64.
__global__ __launch_bounds__(64) void head2_kernel(
    const float* __restrict__ fc2_w, const float* __restrict__ fc2_b,
    float* __restrict__ out)
{
    int b = blockIdx.x, tid = threadIdx.x;
    int c = tid >> 5, lane = tid & 31;
    float acc = 0.f;
    for (int f = lane; f < 300; f += 32)
        acc += g_J[b * 300 + f] * fc2_w[c * 300 + f];
    #pragma unroll
    for (int d = 16; d; d >>= 1) acc += __shfl_xor_sync(0xffffffffu, acc, d);
    if (lane == 0) out[b * 2 + c] = acc + fc2_b[c];
}

// ---------------------------------------------------------------------------
extern "C" void kernel_launch(void* const* d_in, const int* in_sizes, int n_in,
                              void* d_out, int out_size)
{
    const int*   q1     = (const int*)d_in[0];
    const int*   q2     = (const int*)d_in[1];
    const int*   q1_len = (const int*)d_in[2];
    const int*   q2_len = (const int*)d_in[3];
    const float* emb    = (const float*)d_in[4];
    const float* conv_w = (const float*)d_in[5];
    const float* conv_b = (const float*)d_in[6];
    const float* fc0_w  = (const float*)d_in[7];
    const float* fc0_b  = (const float*)d_in[8];
    const float* fc1_w  = (const float*)d_in[9];
    const float* fc1_b  = (const float*)d_in[10];
    const float* fc2_w  = (const float*)d_in[11];
    const float* fc2_b  = (const float*)d_in[12];
    const float* att_w  = (const float*)d_in[13];
    const float* att_b  = (const float*)d_in[14];
    float* out = (float*)d_out;

    const int smC = 48 * 301 * 4 + 48 * 4;

    cudaFuncSetAttribute(encode_tc,   cudaFuncAttributeMaxDynamicSharedMemorySize, SME_TOTAL);
    cudaFuncSetAttribute(joint_tc,    cudaFuncAttributeMaxDynamicSharedMemorySize, SMB_TOTAL);
    cudaFuncSetAttribute(pool_kernel, cudaFuncAttributeMaxDynamicSharedMemorySize, smC);

    prep_all<<<PA_G0 + PA_G1 + PA_G2 + PA_G3, 256>>>(q1, q2, emb, fc0_w, conv_w);
    encode_tc<<<dim3(128, 2), 192, SME_TOTAL>>>(conv_b);
    joint_tc<<<dim3(18, 3, 64), 256, SMB_TOTAL>>>(q1_len, q2_len);
    pool_kernel<<<dim3(2, 64), 512, smC>>>(q1_len, q2_len, att_w, att_b, fc0_b);
    head1_kernel<<<dim3(64, 5), 256>>>(fc1_w, fc1_b);
    head2_kernel<<<64, 64>>>(fc2_w, fc2_b, out);
    (void)in_sizes; (void)n_in; (void)out_size;
}